// round 8
// baseline (speedup 1.0000x reference)
#include <cuda_runtime.h>
#include <cstdint>
#include <math.h>
#include <string.h>

// ---------------- problem constants ----------------
#define BB 4
#define NN 4096
#define PP 32
#define CTOT 256
#define YROWS 30
#define NBV (BB*2048)

// ---------------- device tables (filled via async memcpy each launch) -----
__device__ unsigned long long g_terms[3600];
__device__ unsigned long long g_items[1332];

// ---------------- shared host/device layout tables ----------------
#define N_TRI 27
static const int h_tri[N_TRI][4] = {
  {1,1,0,0},{1,1,1,9},{1,1,2,36},
  {1,2,1,81},{1,2,2,126},{1,2,3,201},
  {1,3,2,306},{1,3,3,411},
  {2,1,1,558},{2,1,2,603},{2,1,3,678},
  {2,2,0,783},{2,2,1,808},{2,2,2,883},{2,2,3,1008},
  {2,3,1,1183},{2,3,2,1288},{2,3,3,1463},
  {3,1,2,1708},{3,1,3,1813},
  {3,2,1,1960},{3,2,2,2065},{3,2,3,2240},
  {3,3,0,2485},{3,3,1,2534},{3,3,2,2681},{3,3,3,2926}
};

struct HSeg { int kind, j, l, cstart, cgoff; };
static const HSeg h_segs[4][11] = {
  { {0,0,0,0,0},{2,1,1,64,0},{2,2,2,112,783},{2,3,3,144,2485},
    {0,0,0,0,0},{0,0,0,0,0},{0,0,0,0,0},{0,0,0,0,0},{0,0,0,0,0},{0,0,0,0,0},{0,0,0,0,0} },
  { {0,1,0,0,0},{1,0,1,48,0},{2,1,1,112,9},{2,2,1,160,558},{2,1,2,192,81},
    {2,2,2,240,808},{2,3,2,272,1960},{2,2,3,288,1183},{2,3,3,320,2534},
    {0,0,0,0,0},{0,0,0,0,0} },
  { {0,2,0,0,0},{1,0,2,32,0},{2,1,1,96,36},{2,2,1,144,603},{2,3,1,176,1708},
    {2,1,2,192,126},{2,2,2,240,883},{2,3,2,272,2065},{2,1,3,288,306},
    {2,2,3,336,1288},{2,3,3,368,2681} },
  { {0,3,0,0,0},{1,0,3,16,0},{2,2,1,80,678},{2,3,1,112,1813},{2,1,2,128,201},
    {2,2,2,176,1008},{2,3,2,208,2240},{2,1,3,224,411},{2,2,3,272,1463},
    {2,3,3,304,2926},{0,0,0,0,0} }
};

static const unsigned char h_lut[4][24] = {
  {0,0,0,0,1,1,1,2,2,3, 0,0,0,0,0,0,0,0,0,0,0,0,0,0},
  {0,0,0,1,1,1,1,2,2,2,3,3,4,4,4,5,5,6,7,7,8, 0,0,0},
  {0,0,1,1,1,1,2,2,2,3,3,4,5,5,5,6,6,7,8,8,8,9,9,10},
  {0,1,1,1,1,2,2,3,4,4,4,5,5,6,7,7,7,8,8,9, 0,0,0,0}
};

static const int h_yoff[4] = {0,4,13,23};
static const int h_coff[4] = {0,16,64,144};
static const int h_chj[4]  = {160,336,384,320};
static const unsigned long long h_outoff[4] = {0ull, 1310720ull, 9568256ull, 25296896ull};
static const int h_jb[4] = {0,1,4,9};

__constant__ int c_bvmul[4] = {160, 1008, 1920, 2240};

// ---------------- host-side CG + table computation ----------------
static double hfact(int n){
  static const double f[21] = {
    1.0,1.0,2.0,6.0,24.0,120.0,720.0,5040.0,40320.0,362880.0,3628800.0,
    39916800.0,479001600.0,6227020800.0,87178291200.0,1307674368000.0,
    20922789888000.0,355687428096000.0,6402373705728000.0,
    121645100408832000.0,2432902008176640000.0 };
  return f[n];
}

static double h_su2cg(int j1,int m1,int j2,int m2,int j3,int m3){
  if(m1+m2 != m3) return 0.0;
  int vmin = -j1+j2+m3; if(-j1+m1 > vmin) vmin = -j1+m1; if(0 > vmin) vmin = 0;
  int vmax = j2+j3+m1; if(j3-j1+j2 < vmax) vmax = j3-j1+j2; if(j3+m3 < vmax) vmax = j3+m3;
  double Cc = sqrt((double)(2*j3+1)*hfact(j3+j1-j2)*hfact(j3-j1+j2)*hfact(j1+j2-j3)
                   *hfact(j3+m3)*hfact(j3-m3)
                   /(hfact(j1+j2+j3+1)*hfact(j1-m1)*hfact(j1+m1)*hfact(j2-m2)*hfact(j2+m2)));
  double S = 0.0;
  for(int v=vmin; v<=vmax; v++){
    double t = hfact(j2+j3+m1-v)*hfact(j1-m1+v)
             /(hfact(v)*hfact(j3-j1+j2-v)*hfact(j3+m3-v)*hfact(v+j1-j2-m3));
    S += ((v+j2+m2)&1) ? -t : t;
  }
  return Cc*S;
}

struct Cpx { double re, im; };
static inline Cpx cmul(Cpx a, Cpx b){ Cpx r; r.re=a.re*b.re-a.im*b.im; r.im=a.re*b.im+a.im*b.re; return r; }

static void h_buildQ(int l, Cpx* q){
  int n = 2*l+1;
  for(int a=0;a<n*n;a++){ q[a].re=0.0; q[a].im=0.0; }
  const double s2 = 0.70710678118654752440;
  for(int m=-l;m<0;m++){
    q[(l+m)*n + (l-m)].re = s2;
    q[(l+m)*n + (l+m)].im = -s2;
  }
  q[l*n+l].re = 1.0;
  for(int m=1;m<=l;m++){
    double sg = (m&1)? -1.0 : 1.0;
    q[(l+m)*n + (l+m)].re = sg*s2;
    q[(l+m)*n + (l-m)].im = sg*s2;
  }
  int r = l & 3;
  Cpx ph = (r==0)? Cpx{1,0} : (r==1)? Cpx{0,-1} : (r==2)? Cpx{-1,0} : Cpx{0,1};
  for(int a=0;a<n*n;a++) q[a] = cmul(ph, q[a]);
}

static float h_cg[3269];
static unsigned long long h_terms[3600];
static unsigned long long h_items[1332];
static int h_lstart[160], h_lcount[160];

static void build_tables(){
  for(int t = 0; t < N_TRI; t++){
    int j = h_tri[t][0], l = h_tri[t][1], J = h_tri[t][2], off = h_tri[t][3];
    int nj = 2*j+1, nl = 2*l+1, nJ = 2*J+1;
    Cpx Q1[49], Q2[49], Q3[49];
    h_buildQ(j, Q1); h_buildQ(l, Q2); h_buildQ(J, Q3);
    double Cs[343];
    for(int i=0;i<nj;i++)
      for(int k=0;k<nl;k++)
        for(int n=0;n<nJ;n++)
          Cs[(i*nl+k)*nJ+n] = h_su2cg(j, i-j, l, k-l, J, n-J);
    for(int jj=0;jj<nj;jj++)
      for(int ll=0;ll<nl;ll++)
        for(int mm=0;mm<nJ;mm++){
          double sx = 0.0;
          for(int i=0;i<nj;i++){
            Cpx a = Q1[i*nj+jj];
            for(int k=0;k<nl;k++){
              int n = i + k - j - l + J;
              if(n < 0 || n >= nJ) continue;
              double c = Cs[(i*nl+k)*nJ + n];
              if(c == 0.0) continue;
              Cpx b  = Q2[k*nl+ll];
              Cpx q3 = Q3[n*nJ+mm];
              Cpx ab = cmul(a, b);
              sx += c * (ab.re*q3.re + ab.im*q3.im);
            }
          }
          h_cg[off + (jj*nl+ll)*nJ + mm] = (float)sx;
        }
  }

  // ---- pass A: list counts ----
  for(int lid = 0; lid < 157; lid++){
    if(lid < 125){
      int k = lid, t = 0;
      for(; t < N_TRI; t++){ int sz = 2*h_tri[t][2]+1; if(k < sz) break; k -= sz; }
      int j = h_tri[t][0], l = h_tri[t][1], J = h_tri[t][2], off = h_tri[t][3];
      int nl = 2*l+1, nJ = 2*J+1, p = k;
      int cnt = 0;
      for(int n = 0; n <= 2*j; n++)
        for(int m = 0; m < nl; m++)
          if(fabsf(h_cg[off + (n*nl+m)*nJ + p]) > 1e-6f) cnt++;
      h_lcount[lid] = cnt;
    } else h_lcount[lid] = 1;
  }
  // starts padded to EVEN indices (16B alignment for vectorized loads)
  { int s = 0;
    for(int i = 0; i < 157; i++){
      h_lstart[i] = s; s += h_lcount[i];
      s = (s + 1) & ~1;
    }
  }
  memset(h_terms, 0, sizeof(h_terms));

  // ---- pass B: terms ----
  for(int lid = 0; lid < 157; lid++){
    int st = h_lstart[lid];
    if(lid < 125){
      int k = lid, t = 0;
      for(; t < N_TRI; t++){ int sz = 2*h_tri[t][2]+1; if(k < sz) break; k -= sz; }
      int j = h_tri[t][0], l = h_tri[t][1], J = h_tri[t][2], off = h_tri[t][3];
      int nl = 2*l+1, nJ = 2*J+1, p = k;
      for(int n = 0; n <= 2*j; n++)
        for(int m = 0; m < nl; m++){
          float c = h_cg[off + (n*nl+m)*nJ + p];
          if(fabsf(c) > 1e-6f){
            int delta = n*(4-j)*CTOT + m*16;
            unsigned u; memcpy(&u, &c, 4);
            h_terms[st++] = ((unsigned long long)(unsigned)delta << 32) | u;
          }
        }
    } else if(lid < 141){
      int k = lid - 125, j = 0;
      while(k >= 2*j+1){ k -= 2*j+1; j++; }
      int delta = k*(4-j)*CTOT;
      float one = 1.0f; unsigned u; memcpy(&u, &one, 4);
      h_terms[st] = ((unsigned long long)(unsigned)delta << 32) | u;
    } else {
      int k = lid - 141, l = 0;
      while(k >= 2*l+1){ k -= 2*l+1; l++; }
      int delta = k*16;
      float one = 1.0f; unsigned u; memcpy(&u, &one, 4);
      h_terms[st] = ((unsigned long long)(unsigned)delta << 32) | u;
    }
  }

  // ---- pass C: item headers (4 channels per item) ----
  for(int idx = 0; idx < 1332; idx++){
    int J, p, cp;
    if(idx < 40)        { J=0; p=0; cp=idx; }
    else if(idx < 292)  { J=1; int r=idx-40;  p=r/84; cp=r-p*84; }
    else if(idx < 772)  { J=2; int r=idx-292; p=r/96; cp=r-p*96; }
    else                { J=3; int r=idx-772; p=r/80; cp=r-p*80; }
    int chan = cp << 2;
    HSeg s = h_segs[J][h_lut[J][chan>>4]];
    int local = chan - s.cstart;
    int i2 = local >> 4;
    int ch = local & 15;

    int lid;
    if(s.kind == 0)      lid = 125 + h_jb[s.j] + p;
    else if(s.kind == 1) lid = 141 + h_jb[s.l] + p;
    else {
      int t = 0;
      for(; t < N_TRI; t++) if(h_tri[t][3] == s.cgoff) break;
      int base = 0;
      for(int q = 0; q < t; q++) base += 2*h_tri[q][2]+1;
      lid = base + p;
    }
    int ybase = (h_yoff[s.j] + i2)*CTOT + h_coff[s.l] + ch;
    int start = h_lstart[lid];
    int cnt   = h_lcount[lid];
    unsigned long long outb = h_outoff[J] + (unsigned long long)p*h_chj[J] + chan;
    unsigned long long h = (unsigned long long)ybase
                         | ((unsigned long long)cnt   << 13)
                         | ((unsigned long long)start << 19)
                         | ((unsigned long long)J     << 31)
                         | (outb << 33);
    h_items[idx] = h;
  }
}

// ---------------- packed f32x2 ops / asm helpers ----------------
__device__ __forceinline__ unsigned long long ffma2(unsigned long long a,
                                                    unsigned long long b,
                                                    unsigned long long c){
  unsigned long long d;
  asm("fma.rn.f32x2 %0, %1, %2, %3;" : "=l"(d) : "l"(a), "l"(b), "l"(c));
  return d;
}
__device__ __forceinline__ unsigned long long fadd2(unsigned long long a,
                                                    unsigned long long b){
  unsigned long long d;
  asm("add.rn.f32x2 %0, %1, %2;" : "=l"(d) : "l"(a), "l"(b));
  return d;
}
__device__ __forceinline__ unsigned long long dup2(unsigned int v){
  unsigned long long d;
  asm("mov.b64 %0, {%1, %1};" : "=l"(d) : "r"(v));
  return d;
}
__device__ __forceinline__ void stcs128(float* p, unsigned long long a,
                                        unsigned long long b){
  asm volatile("st.global.cs.v2.u64 [%0], {%1, %2};" :: "l"(p), "l"(a), "l"(b) : "memory");
}
__device__ __forceinline__ unsigned int smem_u32(const void* p){
  unsigned int a;
  asm("{ .reg .u64 t; cvta.to.shared.u64 t, %1; cvt.u32.u64 %0, t; }"
      : "=r"(a) : "l"(p));
  return a;
}
__device__ __forceinline__ void cpa16(unsigned int saddr, const void* gaddr){
  asm volatile("cp.async.cg.shared.global [%0], [%1], 16;" :: "r"(saddr), "l"(gaddr));
}

// ---------------- main fused kernel ----------------
// 192 threads = (grp: 3 groups of 10 rows) x (cquad: 64 quads of 4 channels)
// smem: single 30720B region `smp` (ysm in phase 2). During phase 1 it holds:
//   floats [0..2047]    : G buffer A (8 patches x 256 ch)
//   floats [2048..4095] : G buffer B
//   floats [4096..6015] : k2 (32p x 30 rows, u64-duplicated) = 7680B
__global__ void __launch_bounds__(192, 6)
shconv_kernel(const float* __restrict__ x0, const float* __restrict__ x1,
              const float* __restrict__ x2, const float* __restrict__ x3,
              const int*  __restrict__ pidx, const float* __restrict__ kern,
              float* __restrict__ out)
{
  __shared__ int rowi[32];
  __shared__ __align__(16) float smp[YROWS*CTOT];   // 30720 B

  const int tid = threadIdx.x;
  const int bv  = blockIdx.x;

  unsigned long long* k2 = (unsigned long long*)&smp[4096];

  if(tid < 32){
    int2 pr = ((const int2*)pidx)[(size_t)bv*PP + tid];
    rowi[tid] = pr.x * NN + pr.y;
  }
  __syncthreads();

  const unsigned int smbase = smem_u32(smp);

  // chunk loader: 8 patches (512 x 16B) into buffer (cc&1)
  auto load_chunk = [&](int cc){
    unsigned int dst = smbase + (unsigned)((cc & 1) * 8192);
    #pragma unroll
    for(int k = 0; k < 3; k++){
      int idx = tid + k*192;
      if(k == 2 && idx >= 512) break;
      int row = idx >> 6;
      int col = idx & 63;
      int c = col * 4;
      const float* bp; int st;
      if(c < 16)       { bp = x0 + c;        st = 16;  }
      else if(c < 64)  { bp = x1 + (c-16);   st = 48;  }
      else if(c < 144) { bp = x2 + (c-64);   st = 80;  }
      else             { bp = x3 + (c-144);  st = 112; }
      cpa16(dst + idx*16, bp + (size_t)rowi[cc*8 + row]*st);
    }
    asm volatile("cp.async.commit_group;");
  };

  load_chunk(0);

  // fill k2 while chunk 0 is in flight (tight layout matches kern layout)
  const float* kb = kern + (size_t)bv * (PP*YROWS);
  #pragma unroll
  for(int i = 0; i < 5; i++){
    int q = tid + i*192;   // 0..959
    unsigned int u = __float_as_uint(kb[q]);
    k2[q] = ((unsigned long long)u << 32) | u;
  }

  load_chunk(1);

  // ---- phase 1: y[30][256] = K[30x32] @ G[32x256], pipelined chunks ----
  const int cquad = tid & 63;
  const int grp   = tid >> 6;          // 0..2
  const int c = cquad * 4;

  ulonglong2 acc[10];
  #pragma unroll
  for(int y = 0; y < 10; y++){ acc[y].x = 0ull; acc[y].y = 0ull; }

  auto compute_chunk = [&](int c4){
    const float* gb = &smp[(c4 & 1) * 2048 + c];
    const unsigned long long* kbase = &k2[(c4*8)*30 + grp*10];
    #pragma unroll
    for(int p8 = 0; p8 < 8; p8++){
      ulonglong2 gv = *(const ulonglong2*)(gb + p8*CTOT);
      const ulonglong2* kp = (const ulonglong2*)(kbase + p8*30);
      #pragma unroll
      for(int y = 0; y < 5; y++){
        ulonglong2 kv = kp[y];
        acc[2*y].x   = ffma2(kv.x, gv.x, acc[2*y].x);
        acc[2*y].y   = ffma2(kv.x, gv.y, acc[2*y].y);
        acc[2*y+1].x = ffma2(kv.y, gv.x, acc[2*y+1].x);
        acc[2*y+1].y = ffma2(kv.y, gv.y, acc[2*y+1].y);
      }
    }
  };

  // c4 = 0
  asm volatile("cp.async.wait_group 1;");
  __syncthreads();
  compute_chunk(0);
  __syncthreads();
  load_chunk(2);
  // c4 = 1
  asm volatile("cp.async.wait_group 1;");
  __syncthreads();
  compute_chunk(1);
  __syncthreads();
  load_chunk(3);
  // c4 = 2
  asm volatile("cp.async.wait_group 1;");
  __syncthreads();
  compute_chunk(2);
  __syncthreads();
  // c4 = 3
  asm volatile("cp.async.wait_group 0;");
  __syncthreads();
  compute_chunk(3);
  __syncthreads();   // all G/k2 reads done; smp becomes ysm

  {
    const int rbase = grp*10;
    #pragma unroll
    for(int y = 0; y < 10; y++)
      *(ulonglong2*)&smp[(rbase+y)*CTOT + c] = acc[y];
  }
  __syncthreads();

  // ---- phase 2: sparse CG program, 4 output channels per item ----
  for(int idx = tid; idx < 1332; idx += 192){
    unsigned long long h = __ldg(&g_items[idx]);
    int ybase = (int)(h & 0x1FFF);
    int cnt   = (int)((h >> 13) & 63);
    int start = (int)((h >> 19) & 4095);
    int J     = (int)((h >> 31) & 3);
    unsigned long long outb = h >> 33;

    unsigned long long a0 = 0ull, a1 = 0ull, b0 = 0ull, b1 = 0ull;
    const unsigned long long* tp = &g_terms[start];
    int t = 0;
    for(; t + 2 <= cnt; t += 2){
      ulonglong2 tt = __ldg((const ulonglong2*)&tp[t]);   // start is even: aligned
      ulonglong2 y0 = *(const ulonglong2*)&smp[ybase + (int)(tt.x >> 32)];
      ulonglong2 y1 = *(const ulonglong2*)&smp[ybase + (int)(tt.y >> 32)];
      unsigned long long c0 = dup2((unsigned int)tt.x);
      unsigned long long c1 = dup2((unsigned int)tt.y);
      a0 = ffma2(c0, y0.x, a0); a1 = ffma2(c0, y0.y, a1);
      b0 = ffma2(c1, y1.x, b0); b1 = ffma2(c1, y1.y, b1);
    }
    if(t < cnt){
      unsigned long long t0 = __ldg(&tp[t]);
      ulonglong2 y0 = *(const ulonglong2*)&smp[ybase + (int)(t0 >> 32)];
      unsigned long long c0 = dup2((unsigned int)t0);
      a0 = ffma2(c0, y0.x, a0); a1 = ffma2(c0, y0.y, a1);
    }
    a0 = fadd2(a0, b0);
    a1 = fadd2(a1, b1);
    size_t o = (size_t)outb + (size_t)bv * (size_t)c_bvmul[J];
    stcs128(out + o, a0, a1);
  }
}

// ---------------- launch ----------------
extern "C" void kernel_launch(void* const* d_in, const int* in_sizes, int n_in,
                              void* d_out, int out_size)
{
  const float* x0   = (const float*)d_in[0];
  const float* x1   = (const float*)d_in[1];
  const float* x2   = (const float*)d_in[2];
  const float* x3   = (const float*)d_in[3];
  const int*   pidx = (const int*)  d_in[4];
  const float* kern = (const float*)d_in[5];
  float* out = (float*)d_out;

  build_tables();

  cudaMemcpyToSymbolAsync(g_terms, h_terms, sizeof(h_terms), 0,
                          cudaMemcpyHostToDevice, 0);
  cudaMemcpyToSymbolAsync(g_items, h_items, sizeof(h_items), 0,
                          cudaMemcpyHostToDevice, 0);

  shconv_kernel<<<NBV, 192>>>(x0, x1, x2, x3, pidx, kern, out);
}

// round 9
// speedup vs baseline: 1.2546x; 1.2546x over previous
#include <cuda_runtime.h>
#include <cstdint>
#include <math.h>
#include <string.h>

// ---------------- problem constants ----------------
#define BB 4
#define NN 4096
#define PP 32
#define CTOT 256
#define YROWS 30
#define NBV (BB*2048)

// ---------------- device tables (filled via async memcpy each launch) -----
__device__ unsigned long long g_terms[3600];
__device__ unsigned long long g_items[333];

// ---------------- shared host/device layout tables ----------------
#define N_TRI 27
static const int h_tri[N_TRI][4] = {
  {1,1,0,0},{1,1,1,9},{1,1,2,36},
  {1,2,1,81},{1,2,2,126},{1,2,3,201},
  {1,3,2,306},{1,3,3,411},
  {2,1,1,558},{2,1,2,603},{2,1,3,678},
  {2,2,0,783},{2,2,1,808},{2,2,2,883},{2,2,3,1008},
  {2,3,1,1183},{2,3,2,1288},{2,3,3,1463},
  {3,1,2,1708},{3,1,3,1813},
  {3,2,1,1960},{3,2,2,2065},{3,2,3,2240},
  {3,3,0,2485},{3,3,1,2534},{3,3,2,2681},{3,3,3,2926}
};

struct HSeg { int kind, j, l, cstart, cgoff; };
static const HSeg h_segs[4][11] = {
  { {0,0,0,0,0},{2,1,1,64,0},{2,2,2,112,783},{2,3,3,144,2485},
    {0,0,0,0,0},{0,0,0,0,0},{0,0,0,0,0},{0,0,0,0,0},{0,0,0,0,0},{0,0,0,0,0},{0,0,0,0,0} },
  { {0,1,0,0,0},{1,0,1,48,0},{2,1,1,112,9},{2,2,1,160,558},{2,1,2,192,81},
    {2,2,2,240,808},{2,3,2,272,1960},{2,2,3,288,1183},{2,3,3,320,2534},
    {0,0,0,0,0},{0,0,0,0,0} },
  { {0,2,0,0,0},{1,0,2,32,0},{2,1,1,96,36},{2,2,1,144,603},{2,3,1,176,1708},
    {2,1,2,192,126},{2,2,2,240,883},{2,3,2,272,2065},{2,1,3,288,306},
    {2,2,3,336,1288},{2,3,3,368,2681} },
  { {0,3,0,0,0},{1,0,3,16,0},{2,2,1,80,678},{2,3,1,112,1813},{2,1,2,128,201},
    {2,2,2,176,1008},{2,3,2,208,2240},{2,1,3,224,411},{2,2,3,272,1463},
    {2,3,3,304,2926},{0,0,0,0,0} }
};

static const unsigned char h_lut[4][24] = {
  {0,0,0,0,1,1,1,2,2,3, 0,0,0,0,0,0,0,0,0,0,0,0,0,0},
  {0,0,0,1,1,1,1,2,2,2,3,3,4,4,4,5,5,6,7,7,8, 0,0,0},
  {0,0,1,1,1,1,2,2,2,3,3,4,5,5,5,6,6,7,8,8,8,9,9,10},
  {0,1,1,1,1,2,2,3,4,4,4,5,5,6,7,7,7,8,8,9, 0,0,0,0}
};

static const int h_yoff[4] = {0,4,13,23};
static const int h_coff[4] = {0,16,64,144};
static const int h_chj[4]  = {160,336,384,320};
static const unsigned long long h_outoff[4] = {0ull, 1310720ull, 9568256ull, 25296896ull};
static const int h_jb[4] = {0,1,4,9};

__constant__ int c_bvmul[4] = {160, 1008, 1920, 2240};

// ---------------- host-side CG + table computation ----------------
static double hfact(int n){
  static const double f[21] = {
    1.0,1.0,2.0,6.0,24.0,120.0,720.0,5040.0,40320.0,362880.0,3628800.0,
    39916800.0,479001600.0,6227020800.0,87178291200.0,1307674368000.0,
    20922789888000.0,355687428096000.0,6402373705728000.0,
    121645100408832000.0,2432902008176640000.0 };
  return f[n];
}

static double h_su2cg(int j1,int m1,int j2,int m2,int j3,int m3){
  if(m1+m2 != m3) return 0.0;
  int vmin = -j1+j2+m3; if(-j1+m1 > vmin) vmin = -j1+m1; if(0 > vmin) vmin = 0;
  int vmax = j2+j3+m1; if(j3-j1+j2 < vmax) vmax = j3-j1+j2; if(j3+m3 < vmax) vmax = j3+m3;
  double Cc = sqrt((double)(2*j3+1)*hfact(j3+j1-j2)*hfact(j3-j1+j2)*hfact(j1+j2-j3)
                   *hfact(j3+m3)*hfact(j3-m3)
                   /(hfact(j1+j2+j3+1)*hfact(j1-m1)*hfact(j1+m1)*hfact(j2-m2)*hfact(j2+m2)));
  double S = 0.0;
  for(int v=vmin; v<=vmax; v++){
    double t = hfact(j2+j3+m1-v)*hfact(j1-m1+v)
             /(hfact(v)*hfact(j3-j1+j2-v)*hfact(j3+m3-v)*hfact(v+j1-j2-m3));
    S += ((v+j2+m2)&1) ? -t : t;
  }
  return Cc*S;
}

struct Cpx { double re, im; };
static inline Cpx cmul(Cpx a, Cpx b){ Cpx r; r.re=a.re*b.re-a.im*b.im; r.im=a.re*b.im+a.im*b.re; return r; }

static void h_buildQ(int l, Cpx* q){
  int n = 2*l+1;
  for(int a=0;a<n*n;a++){ q[a].re=0.0; q[a].im=0.0; }
  const double s2 = 0.70710678118654752440;
  for(int m=-l;m<0;m++){
    q[(l+m)*n + (l-m)].re = s2;
    q[(l+m)*n + (l+m)].im = -s2;
  }
  q[l*n+l].re = 1.0;
  for(int m=1;m<=l;m++){
    double sg = (m&1)? -1.0 : 1.0;
    q[(l+m)*n + (l+m)].re = sg*s2;
    q[(l+m)*n + (l-m)].im = sg*s2;
  }
  int r = l & 3;
  Cpx ph = (r==0)? Cpx{1,0} : (r==1)? Cpx{0,-1} : (r==2)? Cpx{-1,0} : Cpx{0,1};
  for(int a=0;a<n*n;a++) q[a] = cmul(ph, q[a]);
}

static float h_cg[3269];
static unsigned long long h_terms[3600];
static unsigned long long h_items[333];
static int h_lstart[160], h_lcount[160];

static void build_tables(){
  // ---- dense CG table ----
  for(int t = 0; t < N_TRI; t++){
    int j = h_tri[t][0], l = h_tri[t][1], J = h_tri[t][2], off = h_tri[t][3];
    int nj = 2*j+1, nl = 2*l+1, nJ = 2*J+1;
    Cpx Q1[49], Q2[49], Q3[49];
    h_buildQ(j, Q1); h_buildQ(l, Q2); h_buildQ(J, Q3);
    double Cs[343];
    for(int i=0;i<nj;i++)
      for(int k=0;k<nl;k++)
        for(int n=0;n<nJ;n++)
          Cs[(i*nl+k)*nJ+n] = h_su2cg(j, i-j, l, k-l, J, n-J);
    for(int jj=0;jj<nj;jj++)
      for(int ll=0;ll<nl;ll++)
        for(int mm=0;mm<nJ;mm++){
          double sx = 0.0;
          for(int i=0;i<nj;i++){
            Cpx a = Q1[i*nj+jj];
            for(int k=0;k<nl;k++){
              int n = i + k - j - l + J;
              if(n < 0 || n >= nJ) continue;
              double c = Cs[(i*nl+k)*nJ + n];
              if(c == 0.0) continue;
              Cpx b  = Q2[k*nl+ll];
              Cpx q3 = Q3[n*nJ+mm];
              Cpx ab = cmul(a, b);
              sx += c * (ab.re*q3.re + ab.im*q3.im);
            }
          }
          h_cg[off + (jj*nl+ll)*nJ + mm] = (float)sx;
        }
  }

  // ---- pass A: list counts ----
  for(int lid = 0; lid < 157; lid++){
    if(lid < 125){
      int k = lid, t = 0;
      for(; t < N_TRI; t++){ int sz = 2*h_tri[t][2]+1; if(k < sz) break; k -= sz; }
      int j = h_tri[t][0], l = h_tri[t][1], J = h_tri[t][2], off = h_tri[t][3];
      int nl = 2*l+1, nJ = 2*J+1, p = k;
      int cnt = 0;
      for(int n = 0; n <= 2*j; n++)
        for(int m = 0; m < nl; m++)
          if(fabsf(h_cg[off + (n*nl+m)*nJ + p]) > 1e-6f) cnt++;
      h_lcount[lid] = cnt;
    } else h_lcount[lid] = 1;
  }
  // starts padded to EVEN indices (16B alignment for vectorized term loads)
  { int s = 0;
    for(int i = 0; i < 157; i++){
      h_lstart[i] = s; s += h_lcount[i];
      s = (s + 1) & ~1;
    }
  }
  memset(h_terms, 0, sizeof(h_terms));

  // ---- pass B: terms ----
  for(int lid = 0; lid < 157; lid++){
    int st = h_lstart[lid];
    if(lid < 125){
      int k = lid, t = 0;
      for(; t < N_TRI; t++){ int sz = 2*h_tri[t][2]+1; if(k < sz) break; k -= sz; }
      int j = h_tri[t][0], l = h_tri[t][1], J = h_tri[t][2], off = h_tri[t][3];
      int nl = 2*l+1, nJ = 2*J+1, p = k;
      for(int n = 0; n <= 2*j; n++)
        for(int m = 0; m < nl; m++){
          float c = h_cg[off + (n*nl+m)*nJ + p];
          if(fabsf(c) > 1e-6f){
            int delta = n*(4-j)*CTOT + m*16;
            unsigned u; memcpy(&u, &c, 4);
            h_terms[st++] = ((unsigned long long)(unsigned)delta << 32) | u;
          }
        }
    } else if(lid < 141){
      int k = lid - 125, j = 0;
      while(k >= 2*j+1){ k -= 2*j+1; j++; }
      int delta = k*(4-j)*CTOT;
      float one = 1.0f; unsigned u; memcpy(&u, &one, 4);
      h_terms[st] = ((unsigned long long)(unsigned)delta << 32) | u;
    } else {
      int k = lid - 141, l = 0;
      while(k >= 2*l+1){ k -= 2*l+1; l++; }
      int delta = k*16;
      float one = 1.0f; unsigned u; memcpy(&u, &one, 4);
      h_terms[st] = ((unsigned long long)(unsigned)delta << 32) | u;
    }
  }

  // ---- pass C: WIDE item headers (16 channels per item, 333 total) ----
  {
    int w = 0;
    for(int J = 0; J <= 3; J++){
      int nch16 = h_chj[J] / 16;
      for(int p = 0; p < 2*J+1; p++){
        for(int c16 = 0; c16 < nch16; c16++){
          int chan = c16 * 16;
          HSeg s = h_segs[J][h_lut[J][c16]];
          int local = chan - s.cstart;
          int i2 = local >> 4;

          int lid;
          if(s.kind == 0)      lid = 125 + h_jb[s.j] + p;
          else if(s.kind == 1) lid = 141 + h_jb[s.l] + p;
          else {
            int t = 0;
            for(; t < N_TRI; t++) if(h_tri[t][3] == s.cgoff) break;
            int base = 0;
            for(int q = 0; q < t; q++) base += 2*h_tri[q][2]+1;
            lid = base + p;
          }
          int ybase = (h_yoff[s.j] + i2)*CTOT + h_coff[s.l];
          int start = h_lstart[lid];
          int cnt   = h_lcount[lid];
          unsigned long long outb = h_outoff[J] + (unsigned long long)p*h_chj[J] + chan;
          unsigned long long h = (unsigned long long)ybase
                               | ((unsigned long long)cnt   << 13)
                               | ((unsigned long long)start << 19)
                               | ((unsigned long long)J     << 31)
                               | (outb << 33);
          h_items[w++] = h;
        }
      }
    }
  }
}

// ---------------- packed f32x2 ops / asm helpers ----------------
__device__ __forceinline__ unsigned long long ffma2(unsigned long long a,
                                                    unsigned long long b,
                                                    unsigned long long c){
  unsigned long long d;
  asm("fma.rn.f32x2 %0, %1, %2, %3;" : "=l"(d) : "l"(a), "l"(b), "l"(c));
  return d;
}
__device__ __forceinline__ unsigned long long fadd2(unsigned long long a,
                                                    unsigned long long b){
  unsigned long long d;
  asm("add.rn.f32x2 %0, %1, %2;" : "=l"(d) : "l"(a), "l"(b));
  return d;
}
__device__ __forceinline__ unsigned long long dup2(unsigned int v){
  unsigned long long d;
  asm("mov.b64 %0, {%1, %1};" : "=l"(d) : "r"(v));
  return d;
}
__device__ __forceinline__ void stcs128(float* p, unsigned long long a,
                                        unsigned long long b){
  asm volatile("st.global.cs.v2.u64 [%0], {%1, %2};" :: "l"(p), "l"(a), "l"(b) : "memory");
}
__device__ __forceinline__ unsigned int smem_u32(const void* p){
  unsigned int a;
  asm("{ .reg .u64 t; cvta.to.shared.u64 t, %1; cvt.u32.u64 %0, t; }"
      : "=r"(a) : "l"(p));
  return a;
}
__device__ __forceinline__ void cpa16(unsigned int saddr, const void* gaddr){
  asm volatile("cp.async.cg.shared.global [%0], [%1], 16;" :: "r"(saddr), "l"(gaddr));
}

// ---------------- main fused kernel ----------------
// 192 threads = (grp: 3 groups of 10 rows) x (cquad: 64 quads of 4 channels)
// gy: union of G tile [32p x 256ch] (phase 1 input) and ysm [30 x 256] (phase 2)
// k2: tight [p][30] u64-duplicated kernel values (7680 B)
__global__ void __launch_bounds__(192, 5)
shconv_kernel(const float* __restrict__ x0, const float* __restrict__ x1,
              const float* __restrict__ x2, const float* __restrict__ x3,
              const int*  __restrict__ pidx, const float* __restrict__ kern,
              float* __restrict__ out)
{
  __shared__ int rowi[32];
  __shared__ __align__(16) float gy[PP*CTOT];             // 32 KB
  __shared__ __align__(16) unsigned long long k2[PP*YROWS]; // 7.68 KB

  const int tid = threadIdx.x;
  const int bv  = blockIdx.x;

  if(tid < 32){
    int2 pr = ((const int2*)pidx)[(size_t)bv*PP + tid];
    rowi[tid] = pr.x * NN + pr.y;
  }
  __syncthreads();

  // ---- stage G[32][256] into smem via cp.async in one burst ----
  {
    unsigned int gybase = smem_u32(gy);
    #pragma unroll
    for(int k = 0; k < 11; k++){
      int idx = tid + k*192;
      if(k == 10 && idx >= 2048) break;
      int row = idx >> 6;          // patch p
      int col = idx & 63;          // 16B chunk within row
      int c = col * 4;
      const float* bp; int st;
      if(c < 16)       { bp = x0 + c;        st = 16;  }
      else if(c < 64)  { bp = x1 + (c-16);   st = 48;  }
      else if(c < 144) { bp = x2 + (c-64);   st = 80;  }
      else             { bp = x3 + (c-144);  st = 112; }
      cpa16(gybase + idx*16, bp + (size_t)rowi[row]*st);
    }
    asm volatile("cp.async.commit_group;");
  }

  // ---- fill k2 while cp.async is in flight (layout matches kern) ----
  const float* kb = kern + (size_t)bv * (PP*YROWS);
  #pragma unroll
  for(int i = 0; i < 5; i++){
    int q = tid + i*192;   // 0..959
    unsigned int u = __float_as_uint(kb[q]);
    k2[q] = ((unsigned long long)u << 32) | u;
  }
  asm volatile("cp.async.wait_group 0;");
  __syncthreads();

  // ---- phase 1: y[30][256] = K[30x32] @ G[32x256], all operands in smem ----
  const int cquad = tid & 63;
  const int grp   = tid >> 6;          // 0..2
  const int c = cquad * 4;

  ulonglong2 acc[10];
  #pragma unroll
  for(int y = 0; y < 10; y++){ acc[y].x = 0ull; acc[y].y = 0ull; }

  const float* gp = &gy[c];
  const unsigned long long* kg = &k2[grp*10];
  #pragma unroll 4
  for(int p = 0; p < PP; p++){
    ulonglong2 gv = *(const ulonglong2*)(gp + p*CTOT);
    const ulonglong2* kp = (const ulonglong2*)(kg + p*30);
    #pragma unroll
    for(int y = 0; y < 5; y++){
      ulonglong2 kv = kp[y];
      acc[2*y].x   = ffma2(kv.x, gv.x, acc[2*y].x);
      acc[2*y].y   = ffma2(kv.x, gv.y, acc[2*y].y);
      acc[2*y+1].x = ffma2(kv.y, gv.x, acc[2*y+1].x);
      acc[2*y+1].y = ffma2(kv.y, gv.y, acc[2*y+1].y);
    }
  }
  __syncthreads();   // all G reads done before overwriting gy with y

  {
    const int rbase = grp*10;
    #pragma unroll
    for(int y = 0; y < 10; y++)
      *(ulonglong2*)&gy[(rbase+y)*CTOT + c] = acc[y];
  }
  __syncthreads();

  // ---- phase 2: sparse CG program, quad-cooperative 16-ch wide items ----
  // 4 lanes per item; lane k handles channels +4k (contiguous 64B per quad).
  const int lane4 = tid & 3;
  const int ch4   = lane4 * 4;
  for(int widx = tid >> 2; widx < 333; widx += 48){
    unsigned long long h = __ldg(&g_items[widx]);
    int ybase = (int)(h & 0x1FFF) + ch4;
    int cnt   = (int)((h >> 13) & 63);
    int start = (int)((h >> 19) & 4095);
    int J     = (int)((h >> 31) & 3);
    unsigned long long outb = (h >> 33) + (unsigned)ch4;

    unsigned long long a0 = 0ull, a1 = 0ull, b0 = 0ull, b1 = 0ull;
    const unsigned long long* tp = &g_terms[start];
    int t = 0;
    for(; t + 2 <= cnt; t += 2){
      ulonglong2 tt = __ldg((const ulonglong2*)&tp[t]);   // aligned: start even
      ulonglong2 y0 = *(const ulonglong2*)&gy[ybase + (int)(tt.x >> 32)];
      ulonglong2 y1 = *(const ulonglong2*)&gy[ybase + (int)(tt.y >> 32)];
      unsigned long long c0 = dup2((unsigned int)tt.x);
      unsigned long long c1 = dup2((unsigned int)tt.y);
      a0 = ffma2(c0, y0.x, a0); a1 = ffma2(c0, y0.y, a1);
      b0 = ffma2(c1, y1.x, b0); b1 = ffma2(c1, y1.y, b1);
    }
    if(t < cnt){
      unsigned long long t0 = __ldg(&tp[t]);
      ulonglong2 y0 = *(const ulonglong2*)&gy[ybase + (int)(t0 >> 32)];
      unsigned long long c0 = dup2((unsigned int)t0);
      a0 = ffma2(c0, y0.x, a0); a1 = ffma2(c0, y0.y, a1);
    }
    a0 = fadd2(a0, b0);
    a1 = fadd2(a1, b1);
    size_t o = (size_t)outb + (size_t)bv * (size_t)c_bvmul[J];
    stcs128(out + o, a0, a1);
  }
}

// ---------------- launch ----------------
extern "C" void kernel_launch(void* const* d_in, const int* in_sizes, int n_in,
                              void* d_out, int out_size)
{
  const float* x0   = (const float*)d_in[0];
  const float* x1   = (const float*)d_in[1];
  const float* x2   = (const float*)d_in[2];
  const float* x3   = (const float*)d_in[3];
  const int*   pidx = (const int*)  d_in[4];
  const float* kern = (const float*)d_in[5];
  float* out = (float*)d_out;

  build_tables();

  cudaMemcpyToSymbolAsync(g_terms, h_terms, sizeof(h_terms), 0,
                          cudaMemcpyHostToDevice, 0);
  cudaMemcpyToSymbolAsync(g_items, h_items, sizeof(h_items), 0,
                          cudaMemcpyHostToDevice, 0);

  shconv_kernel<<<NBV, 192>>>(x0, x1, x2, x3, pidx, kern, out);
}